// round 6
// baseline (speedup 1.0000x reference)
#include <cuda_runtime.h>
#include <cuda_bf16.h>

// Fixed problem shapes
#define P_FULL   65536          // H*W
#define PN       12544          // sampled points
#define M_TGT    80             // targets
#define K_CLS    134            // classes
#define N_ROWS   400            // bs*Q
#define A_ROWS_P 896            // padded rows (7*128); 2 rows (x, sigmoid) per n
#define MTILES   7
#define NKC      14             // split-K chunks
#define KCHUNK   896            // points per k-chunk
#define KCU32    448            // u32 (bf16x2) per k-chunk
#define SCOLS    64             // u32 per smem stage (=128 points)
#define NSTAGE   7              // stages per k-chunk
#define SPITCH   68             // u32 pitch (68%32==4 -> conflict-free frags)
#define JC       49             // j-chunks for prepY

typedef unsigned int u32;

// ---- static scratch ----
__device__ __nv_bfloat16 g_Y[(size_t)M_TGT * PN];              // 2MB
__device__ float g_Dpart[(size_t)A_ROWS_P * NKC * M_TGT];      // [row][kc][m] 4MB
__device__ float g_sp_part[N_ROWS * NKC];
__device__ float g_sg_part[N_ROWS * NKC];
__device__ int   g_ycnt[M_TGT * JC];

// ---------------------------------------------------------------------------
// K1: build Y bf16 + ysum partial counts. grid (JC, M_TGT) x 256.
// ---------------------------------------------------------------------------
__global__ void hm_prepY_kernel(const float* __restrict__ tgt_masks,
                                const int*   __restrict__ point_idx) {
    const int c = blockIdx.x, m = blockIdx.y;
    const int t = threadIdx.x;
    const int j = c * 256 + t;
    const int pj = __ldg(point_idx + j);
    float v = __ldg(tgt_masks + (size_t)m * P_FULL + pj);
    int on = (v != 0.0f);
    g_Y[(size_t)m * PN + j] = __float2bfloat16_rn(on ? 1.0f : 0.0f);

    unsigned ball = __ballot_sync(0xffffffffu, on);
    __shared__ int wc[8];
    if ((t & 31) == 0) wc[t >> 5] = __popc(ball);
    __syncthreads();
    if (t == 0) {
        int s = 0;
#pragma unroll
        for (int w = 0; w < 8; w++) s += wc[w];
        g_ycnt[m * JC + c] = s;
    }
}

// ---------------------------------------------------------------------------
// K2: fused gather + activation + split-K bf16 GEMM (mma.sync m16n8k16).
// grid (MTILES, NKC) x 256 threads (8 warps). CTA: 128(M) x 80(N) x 896(K),
// staged in 7 slices of 128 points. A gathered from pred_masks on the fly.
// ---------------------------------------------------------------------------
#define SMEM_A_U32 (128 * SPITCH)                  // 8704 u32
#define SMEM_B_U32 (80 * SPITCH)                   // 5440 u32
#define SMEM_K2_BYTES ((SMEM_A_U32 + SMEM_B_U32) * 4 + 512)

__global__ void __launch_bounds__(256)
hm_gemm_kernel(const float* __restrict__ pred_masks,
               const int*   __restrict__ point_idx) {
    extern __shared__ u32 sh[];
    u32* As = sh;                          // [128][68]
    u32* Bs = sh + SMEM_A_U32;             // [80][68]
    float* sp_s = (float*)(sh + SMEM_A_U32 + SMEM_B_U32);  // [64]
    float* sg_s = sp_s + 64;                                // [64]

    const int bm = blockIdx.x;             // m-tile
    const int kc = blockIdx.y;             // k-chunk
    const int t  = threadIdx.x;
    const int warpid = t >> 5;
    const int lane = t & 31;
    const int g    = lane >> 2;
    const int tid4 = lane & 3;
    const int R  = bm * 128;               // first A row of tile
    const int n0 = bm * 64;                // first n of tile

    if (t < 64) { sp_s[t] = 0.0f; sg_s[t] = 0.0f; }

    float d[10][4];
#pragma unroll
    for (int nt = 0; nt < 10; nt++)
#pragma unroll
        for (int q = 0; q < 4; q++) d[nt][q] = 0.0f;

    const u32* __restrict__ Y32 = (const u32*)g_Y;
    const int2* __restrict__ pidx2 = (const int2*)point_idx;
    __syncthreads();

#pragma unroll 1
    for (int ksub = 0; ksub < NSTAGE; ksub++) {
        const int kbase = kc * KCU32 + ksub * SCOLS;   // u32 col base

        // ---- B stage: 80 rows x 64 u32, coalesced ----
#pragma unroll
        for (int i = 0; i < 20; i++) {
            int lin = t + 256 * i;         // 0..5119
            int r = lin >> 6, c = lin & 63;
            Bs[r * SPITCH + c] = Y32[(size_t)r * (PN / 2) + kbase + c];
        }

        // ---- A stage: 64 n-pairs x 64 u32; gather + activations ----
#pragma unroll
        for (int i = 0; i < 16; i++) {
            int idx = t + 256 * i;         // 0..4095
            int p = idx >> 6, c = idx & 63;
            int n = n0 + p;
            float x0 = 0.0f, x1 = 0.0f;
            if (n < N_ROWS) {
                int2 pj = __ldg(pidx2 + kbase + c);
                const float* xrow = pred_masks + (size_t)n * P_FULL;
                x0 = __ldg(xrow + pj.x);
                x1 = __ldg(xrow + pj.y);
            }
            float e0 = __expf(-fabsf(x0));
            float i0 = __fdividef(1.0f, 1.0f + e0);
            float sg0 = (x0 >= 0.0f) ? i0 : e0 * i0;
            float sp0 = fmaxf(x0, 0.0f) + __logf(1.0f + e0);
            float e1 = __expf(-fabsf(x1));
            float i1 = __fdividef(1.0f, 1.0f + e1);
            float sg1 = (x1 >= 0.0f) ? i1 : e1 * i1;
            float sp1 = fmaxf(x1, 0.0f) + __logf(1.0f + e1);

            u32 xl = (u32)__bfloat16_as_ushort(__float2bfloat16_rn(x0));
            u32 xh = (u32)__bfloat16_as_ushort(__float2bfloat16_rn(x1));
            u32 sl = (u32)__bfloat16_as_ushort(__float2bfloat16_rn(sg0));
            u32 shh = (u32)__bfloat16_as_ushort(__float2bfloat16_rn(sg1));
            As[(2 * p)     * SPITCH + c] = xl | (xh << 16);
            As[(2 * p + 1) * SPITCH + c] = sl | (shh << 16);

            // warp-level reduce of sp/sg (whole warp shares the same pair p)
            float sps = sp0 + sp1, sgs = sg0 + sg1;
#pragma unroll
            for (int off = 16; off > 0; off >>= 1) {
                sps += __shfl_xor_sync(0xffffffffu, sps, off);
                sgs += __shfl_xor_sync(0xffffffffu, sgs, off);
            }
            if (lane == 0 && n < N_ROWS) {
                atomicAdd(&sp_s[p], sps);
                atomicAdd(&sg_s[p], sgs);
            }
        }
        __syncthreads();

        // ---- MMA over this 128-point stage ----
        const int wrow = warpid * 16;
#pragma unroll
        for (int ks = 0; ks < 8; ks++) {
            const int kcol = ks * 8;
            const u32* pa = As + (wrow + g) * SPITCH + kcol + tid4;
            u32 a0 = pa[0];
            u32 a1 = pa[8 * SPITCH];
            u32 a2 = pa[4];
            u32 a3 = pa[8 * SPITCH + 4];
#pragma unroll
            for (int nt = 0; nt < 10; nt++) {
                const u32* pb = Bs + (nt * 8 + g) * SPITCH + kcol + tid4;
                u32 b0 = pb[0];
                u32 b1 = pb[4];
                asm volatile(
                    "mma.sync.aligned.m16n8k16.row.col.f32.bf16.bf16.f32 "
                    "{%0,%1,%2,%3}, {%4,%5,%6,%7}, {%8,%9}, {%0,%1,%2,%3};"
                    : "+f"(d[nt][0]), "+f"(d[nt][1]), "+f"(d[nt][2]), "+f"(d[nt][3])
                    : "r"(a0), "r"(a1), "r"(a2), "r"(a3), "r"(b0), "r"(b1));
            }
        }
        __syncthreads();
    }

    // ---- epilogue: partials [row][kc][m] ----
    const int row0 = R + warpid * 16 + g;
#pragma unroll
    for (int nt = 0; nt < 10; nt++) {
        int ncol = nt * 8 + tid4 * 2;
        float* p0 = g_Dpart + ((size_t)row0 * NKC + kc) * M_TGT + ncol;
        float* p8 = g_Dpart + ((size_t)(row0 + 8) * NKC + kc) * M_TGT + ncol;
        p0[0] = d[nt][0]; p0[1] = d[nt][1];
        p8[0] = d[nt][2]; p8[1] = d[nt][3];
    }
    if (t < 64 && n0 + t < N_ROWS) {
        g_sp_part[(n0 + t) * NKC + kc] = sp_s[t];
        g_sg_part[(n0 + t) * NKC + kc] = sg_s[t];
    }
}

// ---------------------------------------------------------------------------
// K3: reduce partials + softmax + cost assembly. grid 400 x 256 threads.
// ---------------------------------------------------------------------------
__global__ void __launch_bounds__(256)
hm_final_kernel(const float* __restrict__ pred_logits,
                const int*   __restrict__ tgt_labels,
                float*       __restrict__ out) {
    const int n = blockIdx.x;
    const int t = threadIdx.x;

    __shared__ float lg[K_CLS];
    __shared__ float rr[128];
    __shared__ float xpart[2][M_TGT];
    __shared__ float spart[2][M_TGT];
    __shared__ float s_mx, s_inv;

    if (t < K_CLS) lg[t] = __ldg(pred_logits + (size_t)n * K_CLS + t);

    // partial xy/sy sums: t = m + 80*s, s in {0,1}; each sums 7 k-chunks
    if (t < 160) {
        const int m = t % M_TGT, s = t / M_TGT;
        const float* px = g_Dpart + ((size_t)(2 * n) * NKC + s * 7) * M_TGT + m;
        const float* ps = g_Dpart + ((size_t)(2 * n + 1) * NKC + s * 7) * M_TGT + m;
        float xs = 0.0f, ss_ = 0.0f;
#pragma unroll
        for (int k = 0; k < 7; k++) {
            xs  += __ldg(px + k * M_TGT);
            ss_ += __ldg(ps + k * M_TGT);
        }
        xpart[s][m] = xs;
        spart[s][m] = ss_;
    }
    __syncthreads();

    // softmax reduction over K=134
    if (t < 128) {
        float v = lg[t];
        if (t < K_CLS - 128) v = fmaxf(v, lg[t + 128]);
        rr[t] = v;
    }
    __syncthreads();
#pragma unroll
    for (int s = 64; s > 0; s >>= 1) {
        if (t < s) rr[t] = fmaxf(rr[t], rr[t + s]);
        __syncthreads();
    }
    if (t == 0) s_mx = rr[0];
    __syncthreads();
    if (t < 128) {
        float v = __expf(lg[t] - s_mx);
        if (t < K_CLS - 128) v += __expf(lg[t + 128] - s_mx);
        rr[t] = v;
    }
    __syncthreads();
#pragma unroll
    for (int s = 64; s > 0; s >>= 1) {
        if (t < s) rr[t] += rr[t + s];
        __syncthreads();
    }
    if (t == 0) s_inv = __fdividef(1.0f, rr[0]);
    __syncthreads();

    if (t < M_TGT) {
        float xy = xpart[0][t] + xpart[1][t];
        float sy = spart[0][t] + spart[1][t];

        float sp = 0.0f, sg = 0.0f;
#pragma unroll
        for (int kc = 0; kc < NKC; kc++) {
            sp += __ldg(g_sp_part + n * NKC + kc);
            sg += __ldg(g_sg_part + n * NKC + kc);
        }
        int yc = 0;
#pragma unroll
        for (int c = 0; c < JC; c++) yc += __ldg(g_ycnt + t * JC + c);

        int lbl = __ldg(tgt_labels + t);
        lbl = min(max(lbl, 0), K_CLS - 1);
        float p = __expf(lg[lbl] - s_mx) * s_inv;

        const float invPn = 1.0f / (float)PN;
        float cost_class = -p;
        float cost_mask  = (sp - xy) * invPn;
        float cost_dice  = 1.0f - (2.0f * sy + 1.0f) / (sg + (float)yc + 1.0f);
        out[(size_t)n * M_TGT + t] =
            2.0f * cost_class + 5.0f * cost_mask + 5.0f * cost_dice;
    }
}

// ---------------------------------------------------------------------------
// Inputs (metadata order):
//   d_in[0] pred_logits f32 (4,100,134)
//   d_in[1] pred_masks  f32 (4,100,256,256)
//   d_in[2] tgt_labels  i32 (80)
//   d_in[3] tgt_masks   f32 (80,256,256)
//   d_in[4] point_idx   i32 (12544)
// out: f32 (4,100,80)
// ---------------------------------------------------------------------------
extern "C" void kernel_launch(void* const* d_in, const int* in_sizes, int n_in,
                              void* d_out, int out_size) {
    const float* pred_logits = (const float*)d_in[0];
    const float* pred_masks  = (const float*)d_in[1];
    const int*   tgt_labels  = (const int*)  d_in[2];
    const float* tgt_masks   = (const float*)d_in[3];
    const int*   point_idx   = (const int*)  d_in[4];
    float* out = (float*)d_out;

    static int smem_set = 0;
    if (!smem_set) {
        cudaFuncSetAttribute(hm_gemm_kernel,
                             cudaFuncAttributeMaxDynamicSharedMemorySize,
                             SMEM_K2_BYTES);
        smem_set = 1;
    }

    dim3 gy(JC, M_TGT);
    hm_prepY_kernel<<<gy, 256>>>(tgt_masks, point_idx);
    dim3 gg(MTILES, NKC);
    hm_gemm_kernel<<<gg, 256, SMEM_K2_BYTES>>>(pred_masks, point_idx);
    hm_final_kernel<<<N_ROWS, 256>>>(pred_logits, tgt_labels, out);
}

// round 7
// speedup vs baseline: 1.7134x; 1.7134x over previous
#include <cuda_runtime.h>
#include <cuda_bf16.h>

// Fixed problem shapes
#define P_FULL   65536          // H*W
#define PN       12544          // sampled points
#define M_TGT    80             // targets
#define K_CLS    134            // classes
#define N_ROWS   400            // bs*Q
#define A_ROWS_P 896            // padded rows (7*128); 2 rows (x, sigmoid) per n
#define MTILES   7
#define KCHUNK   256            // points per k-chunk
#define NKC      (PN / KCHUNK)  // 49
#define JC       49             // j-chunks for prepY

typedef unsigned int u32;

// ---- static scratch (BSS zero-init; g_A rows >= 800 never written => zero) ----
__device__ __nv_bfloat16 g_A[(size_t)A_ROWS_P * PN];           // 22.5MB
__device__ __nv_bfloat16 g_Y[(size_t)M_TGT * PN];              // 2MB
__device__ float g_Dpart[(size_t)A_ROWS_P * NKC * M_TGT];      // [row][kc][m] 14MB
__device__ float g_spsum[2 * N_ROWS];
__device__ float g_sgsum[2 * N_ROWS];
__device__ int   g_ycnt[M_TGT * JC];

// ---------------------------------------------------------------------------
// K1: build Y bf16 + ysum partial counts. grid (49, 20) x 256.
// Each thread: 1 index load + 4 independent gathers (m0..m0+3).
// ---------------------------------------------------------------------------
__global__ void hm_prepY_kernel(const float* __restrict__ tgt_masks,
                                const int*   __restrict__ point_idx) {
    const int c  = blockIdx.x;
    const int m0 = blockIdx.y * 4;
    const int t  = threadIdx.x;
    const int j  = c * 256 + t;
    const int pj = __ldg(point_idx + j);

    float v0 = __ldg(tgt_masks + (size_t)(m0 + 0) * P_FULL + pj);
    float v1 = __ldg(tgt_masks + (size_t)(m0 + 1) * P_FULL + pj);
    float v2 = __ldg(tgt_masks + (size_t)(m0 + 2) * P_FULL + pj);
    float v3 = __ldg(tgt_masks + (size_t)(m0 + 3) * P_FULL + pj);

    __shared__ int wc[4][8];
    int on[4] = {v0 != 0.0f, v1 != 0.0f, v2 != 0.0f, v3 != 0.0f};
#pragma unroll
    for (int k = 0; k < 4; k++) {
        g_Y[(size_t)(m0 + k) * PN + j] =
            __float2bfloat16_rn(on[k] ? 1.0f : 0.0f);
        unsigned ball = __ballot_sync(0xffffffffu, on[k]);
        if ((t & 31) == 0) wc[k][t >> 5] = __popc(ball);
    }
    __syncthreads();
    if (t < 4) {
        int s = 0;
#pragma unroll
        for (int w = 0; w < 8; w++) s += wc[t][w];
        g_ycnt[(m0 + t) * JC + c] = s;
    }
}

// ---------------------------------------------------------------------------
// K2: build A rows (x, sigmoid) bf16 + per-half sp/sg sums.
// grid 800 = (n, half) x 256 threads. int4 index loads, 4 gathers per iter,
// next-iteration index prefetch => MLP ~8.
// ---------------------------------------------------------------------------
__device__ __forceinline__ void act(float x, float& sg, float& sp) {
    float e   = __expf(-fabsf(x));
    float inv = __fdividef(1.0f, 1.0f + e);
    sg = (x >= 0.0f) ? inv : e * inv;
    sp = fmaxf(x, 0.0f) + __logf(1.0f + e);
}
__device__ __forceinline__ u32 packbf(float a, float b) {
    u32 lo = (u32)__bfloat16_as_ushort(__float2bfloat16_rn(a));
    u32 hi = (u32)__bfloat16_as_ushort(__float2bfloat16_rn(b));
    return lo | (hi << 16);
}

__global__ void __launch_bounds__(256)
hm_buildA_kernel(const float* __restrict__ pred_masks,
                 const int*   __restrict__ point_idx) {
    const int n = blockIdx.x >> 1;
    const int h = blockIdx.x & 1;
    const int t = threadIdx.x;
    const float* __restrict__ xrow = pred_masks + (size_t)n * P_FULL;
    const int4* __restrict__ pidx4 = (const int4*)point_idx;
    u32* __restrict__ ax = (u32*)(g_A + (size_t)(2 * n) * PN);
    u32* __restrict__ as = (u32*)(g_A + (size_t)(2 * n + 1) * PN);

    const int jb4 = h * 1568;     // int4 base for this half (1568 int4 = 6272 pts)
    float spsum = 0.0f, sgsum = 0.0f;

    int4 nid = __ldg(pidx4 + jb4 + t);   // prefetch iter 0

#pragma unroll 1
    for (int i = 0; i < 6; i++) {
        int4 id = nid;
        if (i < 5)        nid = __ldg(pidx4 + jb4 + (i + 1) * 256 + t);
        else if (t < 32)  nid = __ldg(pidx4 + jb4 + 1536 + t);   // tail prefetch

        float x0 = __ldg(xrow + id.x);
        float x1 = __ldg(xrow + id.y);
        float x2 = __ldg(xrow + id.z);
        float x3 = __ldg(xrow + id.w);
        float sg0, sp0, sg1, sp1, sg2, sp2, sg3, sp3;
        act(x0, sg0, sp0); act(x1, sg1, sp1);
        act(x2, sg2, sp2); act(x3, sg3, sp3);
        spsum += (sp0 + sp1) + (sp2 + sp3);
        sgsum += (sg0 + sg1) + (sg2 + sg3);

        int col = (jb4 + i * 256 + t) * 2;   // u32 column
        ax[col]     = packbf(x0, x1);
        ax[col + 1] = packbf(x2, x3);
        as[col]     = packbf(sg0, sg1);
        as[col + 1] = packbf(sg2, sg3);
    }
    if (t < 32) {   // tail: 32 int4 = 128 points
        int4 id = nid;
        float x0 = __ldg(xrow + id.x);
        float x1 = __ldg(xrow + id.y);
        float x2 = __ldg(xrow + id.z);
        float x3 = __ldg(xrow + id.w);
        float sg0, sp0, sg1, sp1, sg2, sp2, sg3, sp3;
        act(x0, sg0, sp0); act(x1, sg1, sp1);
        act(x2, sg2, sp2); act(x3, sg3, sp3);
        spsum += (sp0 + sp1) + (sp2 + sp3);
        sgsum += (sg0 + sg1) + (sg2 + sg3);
        int col = (jb4 + 1536 + t) * 2;
        ax[col]     = packbf(x0, x1);
        ax[col + 1] = packbf(x2, x3);
        as[col]     = packbf(sg0, sg1);
        as[col + 1] = packbf(sg2, sg3);
    }

    // block reduce sp/sg
    __shared__ float rp[8], rg[8];
#pragma unroll
    for (int off = 16; off > 0; off >>= 1) {
        spsum += __shfl_xor_sync(0xffffffffu, spsum, off);
        sgsum += __shfl_xor_sync(0xffffffffu, sgsum, off);
    }
    if ((t & 31) == 0) { rp[t >> 5] = spsum; rg[t >> 5] = sgsum; }
    __syncthreads();
    if (t == 0) {
        float sp = 0.0f, sg = 0.0f;
#pragma unroll
        for (int w = 0; w < 8; w++) { sp += rp[w]; sg += rg[w]; }
        g_spsum[n * 2 + h] = sp;
        g_sgsum[n * 2 + h] = sg;
    }
}

// ---------------------------------------------------------------------------
// K3: split-K bf16 GEMM via mma.sync m16n8k16.
// grid (7, 49) x 256 threads. CTA tile 128(M) x 80(N) x 256(K).
// ---------------------------------------------------------------------------
#define SPITCH 132                    // u32 pitch (132%32==4 -> conflict-free)
#define SMEM_A_U32 (128 * SPITCH)
#define SMEM_B_U32 (80 * SPITCH)
#define SMEM_K3_BYTES ((SMEM_A_U32 + SMEM_B_U32) * 4)

__global__ void __launch_bounds__(256)
hm_gemm_kernel() {
    extern __shared__ u32 sh[];
    u32* As = sh;                  // [128][132]
    u32* Bs = sh + SMEM_A_U32;     // [80][132]

    const int bm = blockIdx.x;
    const int kc = blockIdx.y;
    const int t  = threadIdx.x;
    const int warpid = t >> 5;
    const int lane = t & 31;
    const int g    = lane >> 2;
    const int tid4 = lane & 3;

    const u32* __restrict__ A32 = (const u32*)g_A;
    const u32* __restrict__ Y32 = (const u32*)g_Y;
    const int R  = bm * 128;
    const int kw = kc * 128;       // u32 col offset

#pragma unroll
    for (int i = 0; i < 64; i++) {
        int lin = t + 256 * i;
        int r = lin >> 7, cu = lin & 127;
        As[r * SPITCH + cu] = A32[(size_t)(R + r) * (PN / 2) + kw + cu];
    }
#pragma unroll
    for (int i = 0; i < 40; i++) {
        int lin = t + 256 * i;
        int r = lin >> 7, cu = lin & 127;
        Bs[r * SPITCH + cu] = Y32[(size_t)r * (PN / 2) + kw + cu];
    }
    __syncthreads();

    float d[10][4];
#pragma unroll
    for (int nt = 0; nt < 10; nt++)
#pragma unroll
        for (int q = 0; q < 4; q++) d[nt][q] = 0.0f;

    const int wrow = warpid * 16;
#pragma unroll
    for (int ks = 0; ks < 16; ks++) {
        const int kcol = ks * 8;
        const u32* pa = As + (wrow + g) * SPITCH + kcol + tid4;
        u32 a0 = pa[0];
        u32 a1 = pa[8 * SPITCH];
        u32 a2 = pa[4];
        u32 a3 = pa[8 * SPITCH + 4];
#pragma unroll
        for (int nt = 0; nt < 10; nt++) {
            const u32* pb = Bs + (nt * 8 + g) * SPITCH + kcol + tid4;
            u32 b0 = pb[0];
            u32 b1 = pb[4];
            asm volatile(
                "mma.sync.aligned.m16n8k16.row.col.f32.bf16.bf16.f32 "
                "{%0,%1,%2,%3}, {%4,%5,%6,%7}, {%8,%9}, {%0,%1,%2,%3};"
                : "+f"(d[nt][0]), "+f"(d[nt][1]), "+f"(d[nt][2]), "+f"(d[nt][3])
                : "r"(a0), "r"(a1), "r"(a2), "r"(a3), "r"(b0), "r"(b1));
        }
    }

    // partials: [row][kc][m] so the final reduction reads contiguously
    const int row0 = R + wrow + g;
#pragma unroll
    for (int nt = 0; nt < 10; nt++) {
        int ncol = nt * 8 + tid4 * 2;
        float* p0 = g_Dpart + ((size_t)row0 * NKC + kc) * M_TGT + ncol;
        float* p8 = g_Dpart + ((size_t)(row0 + 8) * NKC + kc) * M_TGT + ncol;
        p0[0] = d[nt][0]; p0[1] = d[nt][1];
        p8[0] = d[nt][2]; p8[1] = d[nt][3];
    }
}

// ---------------------------------------------------------------------------
// K4: reduce partials + softmax + cost assembly. grid 400 x 256 threads.
// ---------------------------------------------------------------------------
__global__ void __launch_bounds__(256)
hm_final_kernel(const float* __restrict__ pred_logits,
                const int*   __restrict__ tgt_labels,
                float*       __restrict__ out) {
    const int n = blockIdx.x;
    const int t = threadIdx.x;

    __shared__ float lg[K_CLS];
    __shared__ float rr[128];
    __shared__ float xpart[2][M_TGT];
    __shared__ float spart[2][M_TGT];
    __shared__ float s_mx, s_inv;

    if (t < K_CLS) lg[t] = __ldg(pred_logits + (size_t)n * K_CLS + t);

    // partial xy/sy: t = m + 80*s; s=0 sums kc 0..24, s=1 sums kc 25..48
    if (t < 160) {
        const int m = t % M_TGT, s = t / M_TGT;
        const int k0 = s ? 25 : 0;
        const int kn = s ? 24 : 25;
        const float* px = g_Dpart + ((size_t)(2 * n) * NKC + k0) * M_TGT + m;
        const float* ps = g_Dpart + ((size_t)(2 * n + 1) * NKC + k0) * M_TGT + m;
        float xs = 0.0f, ss_ = 0.0f;
        for (int k = 0; k < kn; k++) {
            xs  += __ldg(px + k * M_TGT);
            ss_ += __ldg(ps + k * M_TGT);
        }
        xpart[s][m] = xs;
        spart[s][m] = ss_;
    }
    __syncthreads();

    // softmax over K=134
    if (t < 128) {
        float v = lg[t];
        if (t < K_CLS - 128) v = fmaxf(v, lg[t + 128]);
        rr[t] = v;
    }
    __syncthreads();
#pragma unroll
    for (int s = 64; s > 0; s >>= 1) {
        if (t < s) rr[t] = fmaxf(rr[t], rr[t + s]);
        __syncthreads();
    }
    if (t == 0) s_mx = rr[0];
    __syncthreads();
    if (t < 128) {
        float v = __expf(lg[t] - s_mx);
        if (t < K_CLS - 128) v += __expf(lg[t + 128] - s_mx);
        rr[t] = v;
    }
    __syncthreads();
#pragma unroll
    for (int s = 64; s > 0; s >>= 1) {
        if (t < s) rr[t] += rr[t + s];
        __syncthreads();
    }
    if (t == 0) s_inv = __fdividef(1.0f, rr[0]);
    __syncthreads();

    if (t < M_TGT) {
        float xy = xpart[0][t] + xpart[1][t];
        float sy = spart[0][t] + spart[1][t];
        float sp = g_spsum[2 * n] + g_spsum[2 * n + 1];
        float sg = g_sgsum[2 * n] + g_sgsum[2 * n + 1];

        int yc = 0;
#pragma unroll
        for (int c = 0; c < JC; c++) yc += __ldg(g_ycnt + t * JC + c);

        int lbl = __ldg(tgt_labels + t);
        lbl = min(max(lbl, 0), K_CLS - 1);
        float p = __expf(lg[lbl] - s_mx) * s_inv;

        const float invPn = 1.0f / (float)PN;
        float cost_class = -p;
        float cost_mask  = (sp - xy) * invPn;
        float cost_dice  = 1.0f - (2.0f * sy + 1.0f) / (sg + (float)yc + 1.0f);
        out[(size_t)n * M_TGT + t] =
            2.0f * cost_class + 5.0f * cost_mask + 5.0f * cost_dice;
    }
}

// ---------------------------------------------------------------------------
// Inputs (metadata order):
//   d_in[0] pred_logits f32 (4,100,134)
//   d_in[1] pred_masks  f32 (4,100,256,256)
//   d_in[2] tgt_labels  i32 (80)
//   d_in[3] tgt_masks   f32 (80,256,256)
//   d_in[4] point_idx   i32 (12544)
// out: f32 (4,100,80)
// ---------------------------------------------------------------------------
extern "C" void kernel_launch(void* const* d_in, const int* in_sizes, int n_in,
                              void* d_out, int out_size) {
    const float* pred_logits = (const float*)d_in[0];
    const float* pred_masks  = (const float*)d_in[1];
    const int*   tgt_labels  = (const int*)  d_in[2];
    const float* tgt_masks   = (const float*)d_in[3];
    const int*   point_idx   = (const int*)  d_in[4];
    float* out = (float*)d_out;

    cudaFuncSetAttribute(hm_gemm_kernel,
                         cudaFuncAttributeMaxDynamicSharedMemorySize,
                         SMEM_K3_BYTES);

    dim3 gy(JC, M_TGT / 4);
    hm_prepY_kernel<<<gy, 256>>>(tgt_masks, point_idx);
    hm_buildA_kernel<<<2 * N_ROWS, 256>>>(pred_masks, point_idx);
    dim3 gg(MTILES, NKC);
    hm_gemm_kernel<<<gg, 256, SMEM_K3_BYTES>>>();
    hm_final_kernel<<<N_ROWS, 256>>>(pred_logits, tgt_labels, out);
}

// round 8
// speedup vs baseline: 1.9197x; 1.1204x over previous
#include <cuda_runtime.h>
#include <cuda_bf16.h>

// Fixed problem shapes
#define P_FULL   65536          // H*W
#define PN       12544          // sampled points
#define M_TGT    80             // targets
#define K_CLS    134            // classes
#define N_ROWS   400            // bs*Q
#define A_ROWS_P 896            // padded rows (14*64); 2 rows (x, sigmoid) per n
#define MTILES   14             // m-tiles of 64 rows
#define NKC      14             // split-K chunks
#define KC_U32   448            // u32 (bf16x2) per k-chunk (=896 points)
#define NSTG     7              // stages per chunk
#define STG_U32  64             // u32 per stage (=128 points)
#define JC       49             // j-chunks for prepY
#define ROW_U32  (PN / 2)       // 6272 u32 per bf16 row

typedef unsigned int u32;

// ---- static scratch (BSS zero-init; g_A rows >= 800 never written => zero) ----
__device__ __nv_bfloat16 g_A[(size_t)A_ROWS_P * PN];           // 22.5MB
__device__ __nv_bfloat16 g_Y[(size_t)M_TGT * PN];              // 2MB
__device__ float g_Dpart[(size_t)A_ROWS_P * NKC * M_TGT];      // [row][kc][m] 4MB
__device__ float g_spsum[2 * N_ROWS];
__device__ float g_sgsum[2 * N_ROWS];
__device__ int   g_ycnt[M_TGT * JC];

// ---------------------------------------------------------------------------
// K1: build Y bf16 + ysum partial counts. grid (49, 20) x 256.
// Each thread: 1 index load + 4 independent gathers (m0..m0+3).
// ---------------------------------------------------------------------------
__global__ void hm_prepY_kernel(const float* __restrict__ tgt_masks,
                                const int*   __restrict__ point_idx) {
    const int c  = blockIdx.x;
    const int m0 = blockIdx.y * 4;
    const int t  = threadIdx.x;
    const int j  = c * 256 + t;
    const int pj = __ldg(point_idx + j);

    float v0 = __ldg(tgt_masks + (size_t)(m0 + 0) * P_FULL + pj);
    float v1 = __ldg(tgt_masks + (size_t)(m0 + 1) * P_FULL + pj);
    float v2 = __ldg(tgt_masks + (size_t)(m0 + 2) * P_FULL + pj);
    float v3 = __ldg(tgt_masks + (size_t)(m0 + 3) * P_FULL + pj);

    __shared__ int wc[4][8];
    int on[4] = {v0 != 0.0f, v1 != 0.0f, v2 != 0.0f, v3 != 0.0f};
#pragma unroll
    for (int k = 0; k < 4; k++) {
        g_Y[(size_t)(m0 + k) * PN + j] =
            __float2bfloat16_rn(on[k] ? 1.0f : 0.0f);
        unsigned ball = __ballot_sync(0xffffffffu, on[k]);
        if ((t & 31) == 0) wc[k][t >> 5] = __popc(ball);
    }
    __syncthreads();
    if (t < 4) {
        int s = 0;
#pragma unroll
        for (int w = 0; w < 8; w++) s += wc[t][w];
        g_ycnt[(m0 + t) * JC + c] = s;
    }
}

// ---------------------------------------------------------------------------
// K2: build A rows (x, sigmoid) bf16 + per-half sp/sg sums.
// grid 800 = (n, half) x 256 threads. int4 index loads, 4 gathers per iter,
// next-iteration index prefetch.
// ---------------------------------------------------------------------------
__device__ __forceinline__ void act(float x, float& sg, float& sp) {
    float e   = __expf(-fabsf(x));
    float inv = __fdividef(1.0f, 1.0f + e);
    sg = (x >= 0.0f) ? inv : e * inv;
    sp = fmaxf(x, 0.0f) + __logf(1.0f + e);
}
__device__ __forceinline__ u32 packbf(float a, float b) {
    u32 lo = (u32)__bfloat16_as_ushort(__float2bfloat16_rn(a));
    u32 hi = (u32)__bfloat16_as_ushort(__float2bfloat16_rn(b));
    return lo | (hi << 16);
}

__global__ void __launch_bounds__(256)
hm_buildA_kernel(const float* __restrict__ pred_masks,
                 const int*   __restrict__ point_idx) {
    const int n = blockIdx.x >> 1;
    const int h = blockIdx.x & 1;
    const int t = threadIdx.x;
    const float* __restrict__ xrow = pred_masks + (size_t)n * P_FULL;
    const int4* __restrict__ pidx4 = (const int4*)point_idx;
    u32* __restrict__ ax = (u32*)(g_A + (size_t)(2 * n) * PN);
    u32* __restrict__ as = (u32*)(g_A + (size_t)(2 * n + 1) * PN);

    const int jb4 = h * 1568;     // int4 base for this half (1568 int4 = 6272 pts)
    float spsum = 0.0f, sgsum = 0.0f;

    int4 nid = __ldg(pidx4 + jb4 + t);   // prefetch iter 0

#pragma unroll 1
    for (int i = 0; i < 6; i++) {
        int4 id = nid;
        if (i < 5)        nid = __ldg(pidx4 + jb4 + (i + 1) * 256 + t);
        else if (t < 32)  nid = __ldg(pidx4 + jb4 + 1536 + t);   // tail prefetch

        float x0 = __ldg(xrow + id.x);
        float x1 = __ldg(xrow + id.y);
        float x2 = __ldg(xrow + id.z);
        float x3 = __ldg(xrow + id.w);
        float sg0, sp0, sg1, sp1, sg2, sp2, sg3, sp3;
        act(x0, sg0, sp0); act(x1, sg1, sp1);
        act(x2, sg2, sp2); act(x3, sg3, sp3);
        spsum += (sp0 + sp1) + (sp2 + sp3);
        sgsum += (sg0 + sg1) + (sg2 + sg3);

        int col = (jb4 + i * 256 + t) * 2;   // u32 column
        ax[col]     = packbf(x0, x1);
        ax[col + 1] = packbf(x2, x3);
        as[col]     = packbf(sg0, sg1);
        as[col + 1] = packbf(sg2, sg3);
    }
    if (t < 32) {   // tail: 32 int4 = 128 points
        int4 id = nid;
        float x0 = __ldg(xrow + id.x);
        float x1 = __ldg(xrow + id.y);
        float x2 = __ldg(xrow + id.z);
        float x3 = __ldg(xrow + id.w);
        float sg0, sp0, sg1, sp1, sg2, sp2, sg3, sp3;
        act(x0, sg0, sp0); act(x1, sg1, sp1);
        act(x2, sg2, sp2); act(x3, sg3, sp3);
        spsum += (sp0 + sp1) + (sp2 + sp3);
        sgsum += (sg0 + sg1) + (sg2 + sg3);
        int col = (jb4 + 1536 + t) * 2;
        ax[col]     = packbf(x0, x1);
        ax[col + 1] = packbf(x2, x3);
        as[col]     = packbf(sg0, sg1);
        as[col + 1] = packbf(sg2, sg3);
    }

    // block reduce sp/sg
    __shared__ float rp[8], rg[8];
#pragma unroll
    for (int off = 16; off > 0; off >>= 1) {
        spsum += __shfl_xor_sync(0xffffffffu, spsum, off);
        sgsum += __shfl_xor_sync(0xffffffffu, sgsum, off);
    }
    if ((t & 31) == 0) { rp[t >> 5] = spsum; rg[t >> 5] = sgsum; }
    __syncthreads();
    if (t == 0) {
        float sp = 0.0f, sg = 0.0f;
#pragma unroll
        for (int w = 0; w < 8; w++) { sp += rp[w]; sg += rg[w]; }
        g_spsum[n * 2 + h] = sp;
        g_sgsum[n * 2 + h] = sg;
    }
}

// ---------------------------------------------------------------------------
// K3: split-K bf16 GEMM via mma.sync m16n8k16.
// grid (14, 14) x 256 threads (8 warps: 4 along M x 2 along N).
// CTA tile: 64(M) x 80(N) x 896(K points), 7 smem stages of 128 points.
// Smem pitch 68 u32 (68%32==4 -> conflict-free fragment loads).
// ---------------------------------------------------------------------------
#define SP 68
#define SMEM_A_U32 (64 * SP)    // 4352
#define SMEM_B_U32 (80 * SP)    // 5440
#define SMEM_K3_BYTES ((SMEM_A_U32 + SMEM_B_U32) * 4)  // 39168

__global__ void __launch_bounds__(256)
hm_gemm_kernel() {
    extern __shared__ u32 sh[];
    u32* As = sh;                  // [64][68]
    u32* Bs = sh + SMEM_A_U32;     // [80][68]

    const int bm = blockIdx.x;     // m-tile (64 rows)
    const int kc = blockIdx.y;     // k-chunk (896 points)
    const int t  = threadIdx.x;
    const int warpid = t >> 5;
    const int lane = t & 31;
    const int g    = lane >> 2;
    const int tid4 = lane & 3;
    const int mw   = warpid & 3;   // m-warp: rows mw*16..mw*16+15
    const int nw   = warpid >> 2;  // n-warp: cols nw*40..nw*40+39

    const u32* __restrict__ A32 = (const u32*)g_A;
    const u32* __restrict__ Y32 = (const u32*)g_Y;
    const int R      = bm * 64;
    const int kwbase = kc * KC_U32;

    float d[5][4];
#pragma unroll
    for (int nt = 0; nt < 5; nt++)
#pragma unroll
        for (int q = 0; q < 4; q++) d[nt][q] = 0.0f;

#pragma unroll 1
    for (int stg = 0; stg < NSTG; stg++) {
        const int kw = kwbase + stg * STG_U32;

        // fill A: 64 rows x 64 u32 (16 u32/thread)
#pragma unroll
        for (int i = 0; i < 16; i++) {
            int lin = t + 256 * i;
            int r = lin >> 6, c = lin & 63;
            As[r * SP + c] = A32[(size_t)(R + r) * ROW_U32 + kw + c];
        }
        // fill B: 80 rows x 64 u32 (20 u32/thread)
#pragma unroll
        for (int i = 0; i < 20; i++) {
            int lin = t + 256 * i;
            int r = lin >> 6, c = lin & 63;
            Bs[r * SP + c] = Y32[(size_t)r * ROW_U32 + kw + c];
        }
        __syncthreads();

        const int wrow = mw * 16;
#pragma unroll
        for (int ks = 0; ks < 8; ks++) {
            const int kcol = ks * 8;
            const u32* pa = As + (wrow + g) * SP + kcol + tid4;
            u32 a0 = pa[0];
            u32 a1 = pa[8 * SP];
            u32 a2 = pa[4];
            u32 a3 = pa[8 * SP + 4];
#pragma unroll
            for (int nt = 0; nt < 5; nt++) {
                const u32* pb = Bs + (nw * 40 + nt * 8 + g) * SP + kcol + tid4;
                u32 b0 = pb[0];
                u32 b1 = pb[4];
                asm volatile(
                    "mma.sync.aligned.m16n8k16.row.col.f32.bf16.bf16.f32 "
                    "{%0,%1,%2,%3}, {%4,%5,%6,%7}, {%8,%9}, {%0,%1,%2,%3};"
                    : "+f"(d[nt][0]), "+f"(d[nt][1]), "+f"(d[nt][2]), "+f"(d[nt][3])
                    : "r"(a0), "r"(a1), "r"(a2), "r"(a3), "r"(b0), "r"(b1));
            }
        }
        __syncthreads();
    }

    // partials: [row][kc][m]
    const int row0 = R + mw * 16 + g;
#pragma unroll
    for (int nt = 0; nt < 5; nt++) {
        int ncol = nw * 40 + nt * 8 + tid4 * 2;
        float* p0 = g_Dpart + ((size_t)row0 * NKC + kc) * M_TGT + ncol;
        float* p8 = g_Dpart + ((size_t)(row0 + 8) * NKC + kc) * M_TGT + ncol;
        p0[0] = d[nt][0]; p0[1] = d[nt][1];
        p8[0] = d[nt][2]; p8[1] = d[nt][3];
    }
}

// ---------------------------------------------------------------------------
// K4: reduce partials + softmax + cost assembly. grid 400 x 256 threads.
// ---------------------------------------------------------------------------
__global__ void __launch_bounds__(256)
hm_final_kernel(const float* __restrict__ pred_logits,
                const int*   __restrict__ tgt_labels,
                float*       __restrict__ out) {
    const int n = blockIdx.x;
    const int t = threadIdx.x;

    __shared__ float lg[K_CLS];
    __shared__ float rr[128];
    __shared__ float xpart[2][M_TGT];
    __shared__ float spart[2][M_TGT];
    __shared__ float s_mx, s_inv;

    if (t < K_CLS) lg[t] = __ldg(pred_logits + (size_t)n * K_CLS + t);

    // partial xy/sy: t = m + 80*s; s sums 7 k-chunks each
    if (t < 160) {
        const int m = t % M_TGT, s = t / M_TGT;
        const int k0 = s * 7;
        const float* px = g_Dpart + ((size_t)(2 * n) * NKC + k0) * M_TGT + m;
        const float* ps = g_Dpart + ((size_t)(2 * n + 1) * NKC + k0) * M_TGT + m;
        float xs = 0.0f, ss_ = 0.0f;
#pragma unroll
        for (int k = 0; k < 7; k++) {
            xs  += __ldg(px + k * M_TGT);
            ss_ += __ldg(ps + k * M_TGT);
        }
        xpart[s][m] = xs;
        spart[s][m] = ss_;
    }
    __syncthreads();

    // softmax over K=134
    if (t < 128) {
        float v = lg[t];
        if (t < K_CLS - 128) v = fmaxf(v, lg[t + 128]);
        rr[t] = v;
    }
    __syncthreads();
#pragma unroll
    for (int s = 64; s > 0; s >>= 1) {
        if (t < s) rr[t] = fmaxf(rr[t], rr[t + s]);
        __syncthreads();
    }
    if (t == 0) s_mx = rr[0];
    __syncthreads();
    if (t < 128) {
        float v = __expf(lg[t] - s_mx);
        if (t < K_CLS - 128) v += __expf(lg[t + 128] - s_mx);
        rr[t] = v;
    }
    __syncthreads();
#pragma unroll
    for (int s = 64; s > 0; s >>= 1) {
        if (t < s) rr[t] += rr[t + s];
        __syncthreads();
    }
    if (t == 0) s_inv = __fdividef(1.0f, rr[0]);
    __syncthreads();

    if (t < M_TGT) {
        float xy = xpart[0][t] + xpart[1][t];
        float sy = spart[0][t] + spart[1][t];
        float sp = g_spsum[2 * n] + g_spsum[2 * n + 1];
        float sg = g_sgsum[2 * n] + g_sgsum[2 * n + 1];

        int yc = 0;
#pragma unroll
        for (int c = 0; c < JC; c++) yc += __ldg(g_ycnt + t * JC + c);

        int lbl = __ldg(tgt_labels + t);
        lbl = min(max(lbl, 0), K_CLS - 1);
        float p = __expf(lg[lbl] - s_mx) * s_inv;

        const float invPn = 1.0f / (float)PN;
        float cost_class = -p;
        float cost_mask  = (sp - xy) * invPn;
        float cost_dice  = 1.0f - (2.0f * sy + 1.0f) / (sg + (float)yc + 1.0f);
        out[(size_t)n * M_TGT + t] =
            2.0f * cost_class + 5.0f * cost_mask + 5.0f * cost_dice;
    }
}

// ---------------------------------------------------------------------------
// Inputs (metadata order):
//   d_in[0] pred_logits f32 (4,100,134)
//   d_in[1] pred_masks  f32 (4,100,256,256)
//   d_in[2] tgt_labels  i32 (80)
//   d_in[3] tgt_masks   f32 (80,256,256)
//   d_in[4] point_idx   i32 (12544)
// out: f32 (4,100,80)
// ---------------------------------------------------------------------------
extern "C" void kernel_launch(void* const* d_in, const int* in_sizes, int n_in,
                              void* d_out, int out_size) {
    const float* pred_logits = (const float*)d_in[0];
    const float* pred_masks  = (const float*)d_in[1];
    const int*   tgt_labels  = (const int*)  d_in[2];
    const float* tgt_masks   = (const float*)d_in[3];
    const int*   point_idx   = (const int*)  d_in[4];
    float* out = (float*)d_out;

    dim3 gy(JC, M_TGT / 4);
    hm_prepY_kernel<<<gy, 256>>>(tgt_masks, point_idx);
    hm_buildA_kernel<<<2 * N_ROWS, 256>>>(pred_masks, point_idx);
    dim3 gg(MTILES, NKC);
    hm_gemm_kernel<<<gg, 256, SMEM_K3_BYTES>>>();
    hm_final_kernel<<<N_ROWS, 256>>>(pred_logits, tgt_labels, out);
}

// round 9
// speedup vs baseline: 2.2991x; 1.1976x over previous
#include <cuda_runtime.h>
#include <cuda_bf16.h>

// Fixed problem shapes
#define P_FULL   65536          // H*W
#define PN       12544          // sampled points
#define M_TGT    80             // targets
#define K_CLS    134            // classes
#define N_ROWS   400            // bs*Q
#define A_ROWS_P 896            // padded rows (14*64); 2 rows (x, sigmoid) per n
#define MTILES   14             // m-tiles of 64 rows
#define NKC      14             // split-K chunks
#define KC_U32   448            // u32 (bf16x2) per k-chunk (=896 points)
#define NSTG     7              // stages per chunk
#define JC       49             // j-chunks for prepY
#define ROW_U32  (PN / 2)       // 6272 u32 per bf16 row
#define NWORDS   (P_FULL / 32)  // 2048 bitmap words

typedef unsigned int u32;

// ---- static scratch (BSS zero-init) ----
__device__ __align__(256) __nv_bfloat16 g_A[(size_t)A_ROWS_P * PN];  // 22.5MB
__device__ __align__(256) __nv_bfloat16 g_Y[(size_t)M_TGT * PN];     // 2MB
__device__ float g_Dpart[(size_t)A_ROWS_P * NKC * M_TGT];            // [row][kc][m] 4MB
__device__ float g_spsum[2 * N_ROWS];
__device__ float g_sgsum[2 * N_ROWS];
__device__ int   g_ycnt[M_TGT * JC];
__device__ u32   g_bmp[NWORDS];            // sampled-pixel bitmap (idempotent set)
__device__ int   g_wpre[NWORDS];           // exclusive prefix of word popcounts
__device__ __align__(16) int g_sorted[PN]; // sampled pixels in ascending order

// ---------------------------------------------------------------------------
// K0: bitmap of sampled pixels. atomicOr is idempotent => deterministic
// across graph replays (same input bits each time, never cleared).
// ---------------------------------------------------------------------------
__global__ void hm_bitmap_kernel(const int* __restrict__ point_idx) {
    int j = blockIdx.x * 256 + threadIdx.x;   // grid 49 x 256 = 12544
    int p = __ldg(point_idx + j);
    atomicOr(&g_bmp[p >> 5], 1u << (p & 31));
}

// ---------------------------------------------------------------------------
// K1: exclusive prefix over word popcounts. 1 CTA x 512 threads, 4 words each.
// ---------------------------------------------------------------------------
__global__ void hm_scan_kernel() {
    __shared__ int s[512];
    const int t = threadIdx.x;
    const int base = t * 4;
    int p0 = __popc(g_bmp[base + 0]);
    int p1 = __popc(g_bmp[base + 1]);
    int p2 = __popc(g_bmp[base + 2]);
    int p3 = __popc(g_bmp[base + 3]);
    int c = p0 + p1 + p2 + p3;
    s[t] = c;
    __syncthreads();
    for (int off = 1; off < 512; off <<= 1) {
        int v = (t >= off) ? s[t - off] : 0;
        __syncthreads();
        s[t] += v;
        __syncthreads();
    }
    int excl = s[t] - c;
    g_wpre[base + 0] = excl;
    g_wpre[base + 1] = excl + p0;
    g_wpre[base + 2] = excl + p0 + p1;
    g_wpre[base + 3] = excl + p0 + p1 + p2;
}

// ---------------------------------------------------------------------------
// K2: emit sorted pixel list. grid 8 x 256 = 2048 threads (one per word).
// ---------------------------------------------------------------------------
__global__ void hm_emit_kernel() {
    int w = blockIdx.x * 256 + threadIdx.x;
    u32 bits = g_bmp[w];
    int r = g_wpre[w];
    while (bits) {
        int b = __ffs(bits) - 1;
        g_sorted[r++] = w * 32 + b;
        bits &= bits - 1;
    }
}

// ---------------------------------------------------------------------------
// K3: build Y bf16 + ysum partial counts (sorted point order). grid (49,20).
// ---------------------------------------------------------------------------
__global__ void hm_prepY_kernel(const float* __restrict__ tgt_masks) {
    const int c  = blockIdx.x;
    const int m0 = blockIdx.y * 4;
    const int t  = threadIdx.x;
    const int j  = c * 256 + t;
    const int pj = __ldg(g_sorted + j);

    float v0 = __ldg(tgt_masks + (size_t)(m0 + 0) * P_FULL + pj);
    float v1 = __ldg(tgt_masks + (size_t)(m0 + 1) * P_FULL + pj);
    float v2 = __ldg(tgt_masks + (size_t)(m0 + 2) * P_FULL + pj);
    float v3 = __ldg(tgt_masks + (size_t)(m0 + 3) * P_FULL + pj);

    __shared__ int wc[4][8];
    int on[4] = {v0 != 0.0f, v1 != 0.0f, v2 != 0.0f, v3 != 0.0f};
#pragma unroll
    for (int k = 0; k < 4; k++) {
        g_Y[(size_t)(m0 + k) * PN + j] =
            __float2bfloat16_rn(on[k] ? 1.0f : 0.0f);
        unsigned ball = __ballot_sync(0xffffffffu, on[k]);
        if ((t & 31) == 0) wc[k][t >> 5] = __popc(ball);
    }
    __syncthreads();
    if (t < 4) {
        int s = 0;
#pragma unroll
        for (int w = 0; w < 8; w++) s += wc[t][w];
        g_ycnt[(m0 + t) * JC + c] = s;
    }
}

// ---------------------------------------------------------------------------
// K4: build A rows (x, sigmoid) bf16 + per-half sp/sg sums (sorted order).
// grid 800 = (n, half) x 256 threads.
// ---------------------------------------------------------------------------
__device__ __forceinline__ void act(float x, float& sg, float& sp) {
    float e   = __expf(-fabsf(x));
    float inv = __fdividef(1.0f, 1.0f + e);
    sg = (x >= 0.0f) ? inv : e * inv;
    sp = fmaxf(x, 0.0f) + __logf(1.0f + e);
}
__device__ __forceinline__ u32 packbf(float a, float b) {
    u32 lo = (u32)__bfloat16_as_ushort(__float2bfloat16_rn(a));
    u32 hi = (u32)__bfloat16_as_ushort(__float2bfloat16_rn(b));
    return lo | (hi << 16);
}

__global__ void __launch_bounds__(256)
hm_buildA_kernel(const float* __restrict__ pred_masks) {
    const int n = blockIdx.x >> 1;
    const int h = blockIdx.x & 1;
    const int t = threadIdx.x;
    const float* __restrict__ xrow = pred_masks + (size_t)n * P_FULL;
    const int4* __restrict__ pidx4 = (const int4*)g_sorted;
    u32* __restrict__ ax = (u32*)(g_A + (size_t)(2 * n) * PN);
    u32* __restrict__ as = (u32*)(g_A + (size_t)(2 * n + 1) * PN);

    const int jb4 = h * 1568;     // int4 base (1568 int4 = 6272 points per half)
    float spsum = 0.0f, sgsum = 0.0f;

    int4 nid = __ldg(pidx4 + jb4 + t);

#pragma unroll 1
    for (int i = 0; i < 6; i++) {
        int4 id = nid;
        if (i < 5)        nid = __ldg(pidx4 + jb4 + (i + 1) * 256 + t);
        else if (t < 32)  nid = __ldg(pidx4 + jb4 + 1536 + t);

        float x0 = __ldg(xrow + id.x);
        float x1 = __ldg(xrow + id.y);
        float x2 = __ldg(xrow + id.z);
        float x3 = __ldg(xrow + id.w);
        float sg0, sp0, sg1, sp1, sg2, sp2, sg3, sp3;
        act(x0, sg0, sp0); act(x1, sg1, sp1);
        act(x2, sg2, sp2); act(x3, sg3, sp3);
        spsum += (sp0 + sp1) + (sp2 + sp3);
        sgsum += (sg0 + sg1) + (sg2 + sg3);

        int col = (jb4 + i * 256 + t) * 2;
        ax[col]     = packbf(x0, x1);
        ax[col + 1] = packbf(x2, x3);
        as[col]     = packbf(sg0, sg1);
        as[col + 1] = packbf(sg2, sg3);
    }
    if (t < 32) {
        int4 id = nid;
        float x0 = __ldg(xrow + id.x);
        float x1 = __ldg(xrow + id.y);
        float x2 = __ldg(xrow + id.z);
        float x3 = __ldg(xrow + id.w);
        float sg0, sp0, sg1, sp1, sg2, sp2, sg3, sp3;
        act(x0, sg0, sp0); act(x1, sg1, sp1);
        act(x2, sg2, sp2); act(x3, sg3, sp3);
        spsum += (sp0 + sp1) + (sp2 + sp3);
        sgsum += (sg0 + sg1) + (sg2 + sg3);
        int col = (jb4 + 1536 + t) * 2;
        ax[col]     = packbf(x0, x1);
        ax[col + 1] = packbf(x2, x3);
        as[col]     = packbf(sg0, sg1);
        as[col + 1] = packbf(sg2, sg3);
    }

    __shared__ float rp[8], rg[8];
#pragma unroll
    for (int off = 16; off > 0; off >>= 1) {
        spsum += __shfl_xor_sync(0xffffffffu, spsum, off);
        sgsum += __shfl_xor_sync(0xffffffffu, sgsum, off);
    }
    if ((t & 31) == 0) { rp[t >> 5] = spsum; rg[t >> 5] = sgsum; }
    __syncthreads();
    if (t == 0) {
        float sp = 0.0f, sg = 0.0f;
#pragma unroll
        for (int w = 0; w < 8; w++) { sp += rp[w]; sg += rg[w]; }
        g_spsum[n * 2 + h] = sp;
        g_sgsum[n * 2 + h] = sg;
    }
}

// ---------------------------------------------------------------------------
// K5: split-K bf16 GEMM, cp.async double-buffered pipeline.
// grid (14, 14) x 256 threads (4 m-warps x 2 n-warps).
// CTA tile 64(M) x 80(N) x 896(K points), 7 stages of 128 points.
// ---------------------------------------------------------------------------
#define SP        68
#define ABUF_U32  (64 * SP)               // 4352
#define BBUF_U32  (80 * SP)               // 5440
#define STAGE_U32 (ABUF_U32 + BBUF_U32)   // 9792
#define SMEM_K5_BYTES (2 * STAGE_U32 * 4) // 78336

__device__ __forceinline__ void cp16(u32* smem_dst, const u32* gsrc) {
    u32 sa = (u32)__cvta_generic_to_shared(smem_dst);
    asm volatile("cp.async.cg.shared.global [%0], [%1], 16;\n"
                 :: "r"(sa), "l"(gsrc));
}

__global__ void __launch_bounds__(256)
hm_gemm_kernel() {
    extern __shared__ u32 sh[];

    const int bm = blockIdx.x;
    const int kc = blockIdx.y;
    const int t  = threadIdx.x;
    const int warpid = t >> 5;
    const int lane = t & 31;
    const int g    = lane >> 2;
    const int tid4 = lane & 3;
    const int mw   = warpid & 3;
    const int nw   = warpid >> 2;

    const u32* __restrict__ A32 = (const u32*)g_A;
    const u32* __restrict__ Y32 = (const u32*)g_Y;
    const int R      = bm * 64;
    const int kwbase = kc * KC_U32;

    // precompute this thread's 9 copy slots (2304 16B ops / 256 threads)
    // id < 1024: A tile (64 rows x 16 slots); else B tile (80 rows x 16 slots)
#define ISSUE_STAGE(stg)                                                      \
    do {                                                                      \
        u32* dst = sh + ((stg) & 1) * STAGE_U32;                              \
        const int kw = kwbase + (stg) * 64;                                   \
        _Pragma("unroll")                                                     \
        for (int i = 0; i < 9; i++) {                                         \
            int id = t + 256 * i;                                             \
            if (id < 1024) {                                                  \
                int r = id >> 4, c = (id & 15) * 4;                           \
                cp16(dst + r * SP + c,                                        \
                     A32 + (size_t)(R + r) * ROW_U32 + kw + c);               \
            } else {                                                          \
                int id2 = id - 1024;                                          \
                int r = id2 >> 4, c = (id2 & 15) * 4;                         \
                cp16(dst + ABUF_U32 + r * SP + c,                             \
                     Y32 + (size_t)r * ROW_U32 + kw + c);                     \
            }                                                                 \
        }                                                                     \
        asm volatile("cp.async.commit_group;\n");                             \
    } while (0)

    float d[5][4];
#pragma unroll
    for (int nt = 0; nt < 5; nt++)
#pragma unroll
        for (int q = 0; q < 4; q++) d[nt][q] = 0.0f;

    ISSUE_STAGE(0);

#pragma unroll 1
    for (int stg = 0; stg < NSTG; stg++) {
        if (stg + 1 < NSTG) {
            ISSUE_STAGE(stg + 1);
            asm volatile("cp.async.wait_group 1;\n");
        } else {
            asm volatile("cp.async.wait_group 0;\n");
        }
        __syncthreads();

        const u32* As = sh + (stg & 1) * STAGE_U32;
        const u32* Bs = As + ABUF_U32;
        const int wrow = mw * 16;
#pragma unroll
        for (int ks = 0; ks < 8; ks++) {
            const int kcol = ks * 8;
            const u32* pa = As + (wrow + g) * SP + kcol + tid4;
            u32 a0 = pa[0];
            u32 a1 = pa[8 * SP];
            u32 a2 = pa[4];
            u32 a3 = pa[8 * SP + 4];
#pragma unroll
            for (int nt = 0; nt < 5; nt++) {
                const u32* pb = Bs + (nw * 40 + nt * 8 + g) * SP + kcol + tid4;
                u32 b0 = pb[0];
                u32 b1 = pb[4];
                asm volatile(
                    "mma.sync.aligned.m16n8k16.row.col.f32.bf16.bf16.f32 "
                    "{%0,%1,%2,%3}, {%4,%5,%6,%7}, {%8,%9}, {%0,%1,%2,%3};"
                    : "+f"(d[nt][0]), "+f"(d[nt][1]), "+f"(d[nt][2]), "+f"(d[nt][3])
                    : "r"(a0), "r"(a1), "r"(a2), "r"(a3), "r"(b0), "r"(b1));
            }
        }
        __syncthreads();
    }

    // partials: [row][kc][m]
    const int row0 = R + mw * 16 + g;
#pragma unroll
    for (int nt = 0; nt < 5; nt++) {
        int ncol = nw * 40 + nt * 8 + tid4 * 2;
        float* p0 = g_Dpart + ((size_t)row0 * NKC + kc) * M_TGT + ncol;
        float* p8 = g_Dpart + ((size_t)(row0 + 8) * NKC + kc) * M_TGT + ncol;
        p0[0] = d[nt][0]; p0[1] = d[nt][1];
        p8[0] = d[nt][2]; p8[1] = d[nt][3];
    }
}

// ---------------------------------------------------------------------------
// K6: reduce partials + softmax + cost assembly. grid 400 x 256 threads.
// ---------------------------------------------------------------------------
__global__ void __launch_bounds__(256)
hm_final_kernel(const float* __restrict__ pred_logits,
                const int*   __restrict__ tgt_labels,
                float*       __restrict__ out) {
    const int n = blockIdx.x;
    const int t = threadIdx.x;

    __shared__ float lg[K_CLS];
    __shared__ float rr[128];
    __shared__ float xpart[2][M_TGT];
    __shared__ float spart[2][M_TGT];
    __shared__ float s_mx, s_inv;

    if (t < K_CLS) lg[t] = __ldg(pred_logits + (size_t)n * K_CLS + t);

    if (t < 160) {
        const int m = t % M_TGT, s = t / M_TGT;
        const int k0 = s * 7;
        const float* px = g_Dpart + ((size_t)(2 * n) * NKC + k0) * M_TGT + m;
        const float* ps = g_Dpart + ((size_t)(2 * n + 1) * NKC + k0) * M_TGT + m;
        float xs = 0.0f, ss_ = 0.0f;
#pragma unroll
        for (int k = 0; k < 7; k++) {
            xs  += __ldg(px + k * M_TGT);
            ss_ += __ldg(ps + k * M_TGT);
        }
        xpart[s][m] = xs;
        spart[s][m] = ss_;
    }
    __syncthreads();

    if (t < 128) {
        float v = lg[t];
        if (t < K_CLS - 128) v = fmaxf(v, lg[t + 128]);
        rr[t] = v;
    }
    __syncthreads();
#pragma unroll
    for (int s = 64; s > 0; s >>= 1) {
        if (t < s) rr[t] = fmaxf(rr[t], rr[t + s]);
        __syncthreads();
    }
    if (t == 0) s_mx = rr[0];
    __syncthreads();
    if (t < 128) {
        float v = __expf(lg[t] - s_mx);
        if (t < K_CLS - 128) v += __expf(lg[t + 128] - s_mx);
        rr[t] = v;
    }
    __syncthreads();
#pragma unroll
    for (int s = 64; s > 0; s >>= 1) {
        if (t < s) rr[t] += rr[t + s];
        __syncthreads();
    }
    if (t == 0) s_inv = __fdividef(1.0f, rr[0]);
    __syncthreads();

    if (t < M_TGT) {
        float xy = xpart[0][t] + xpart[1][t];
        float sy = spart[0][t] + spart[1][t];
        float sp = g_spsum[2 * n] + g_spsum[2 * n + 1];
        float sg = g_sgsum[2 * n] + g_sgsum[2 * n + 1];

        int yc = 0;
#pragma unroll
        for (int c = 0; c < JC; c++) yc += __ldg(g_ycnt + t * JC + c);

        int lbl = __ldg(tgt_labels + t);
        lbl = min(max(lbl, 0), K_CLS - 1);
        float p = __expf(lg[lbl] - s_mx) * s_inv;

        const float invPn = 1.0f / (float)PN;
        float cost_class = -p;
        float cost_mask  = (sp - xy) * invPn;
        float cost_dice  = 1.0f - (2.0f * sy + 1.0f) / (sg + (float)yc + 1.0f);
        out[(size_t)n * M_TGT + t] =
            2.0f * cost_class + 5.0f * cost_mask + 5.0f * cost_dice;
    }
}

// ---------------------------------------------------------------------------
// Inputs (metadata order):
//   d_in[0] pred_logits f32 (4,100,134)
//   d_in[1] pred_masks  f32 (4,100,256,256)
//   d_in[2] tgt_labels  i32 (80)
//   d_in[3] tgt_masks   f32 (80,256,256)
//   d_in[4] point_idx   i32 (12544)
// out: f32 (4,100,80)
// ---------------------------------------------------------------------------
extern "C" void kernel_launch(void* const* d_in, const int* in_sizes, int n_in,
                              void* d_out, int out_size) {
    const float* pred_logits = (const float*)d_in[0];
    const float* pred_masks  = (const float*)d_in[1];
    const int*   tgt_labels  = (const int*)  d_in[2];
    const float* tgt_masks   = (const float*)d_in[3];
    const int*   point_idx   = (const int*)  d_in[4];
    float* out = (float*)d_out;

    static int smem_set = 0;
    if (!smem_set) {
        cudaFuncSetAttribute(hm_gemm_kernel,
                             cudaFuncAttributeMaxDynamicSharedMemorySize,
                             SMEM_K5_BYTES);
        smem_set = 1;
    }

    hm_bitmap_kernel<<<49, 256>>>(point_idx);
    hm_scan_kernel<<<1, 512>>>();
    hm_emit_kernel<<<8, 256>>>();
    dim3 gy(JC, M_TGT / 4);
    hm_prepY_kernel<<<gy, 256>>>(tgt_masks);
    hm_buildA_kernel<<<2 * N_ROWS, 256>>>(pred_masks);
    dim3 gg(MTILES, NKC);
    hm_gemm_kernel<<<gg, 256, SMEM_K5_BYTES>>>();
    hm_final_kernel<<<N_ROWS, 256>>>(pred_logits, tgt_labels, out);
}